// round 11
// baseline (speedup 1.0000x reference)
#include <cuda_runtime.h>
#include <cstdint>

// Problem constants (fixed shapes from reference)
#define B_ROWS 16384
#define T_LEN  4096
#define WORDS  (T_LEN / 32)    // 128 mask words per row
#define CHUNKS (T_LEN / 128)   // 32 warp-chunks (128 elems each) per row
#define THREADS 256
#define ROW_BYTES (T_LEN * 4)  // 16 KB

// Spread 8 bits (positions 0..7) to positions 0,4,8,...,28.
__device__ __forceinline__ uint32_t spread4(uint32_t x)
{
    x &= 0xffu;
    x = (x | (x << 12)) & 0x000F000Fu;
    x = (x | (x << 6))  & 0x03030303u;
    x = (x | (x << 3))  & 0x11111111u;
    return x;
}

__global__ void __launch_bounds__(THREADS)
yawning_adjust_kernel(const float* __restrict__ drowsiness,
                      const int* __restrict__ gesture,
                      float* __restrict__ out)
{
    __shared__ alignas(128) int4 sbuf[T_LEN / 4];   // 16 KB row stage
    __shared__ alignas(8) uint64_t mbar;
    __shared__ uint32_t sball[CHUNKS * 4];          // raw interleaved ballots
    __shared__ int      sred[THREADS / 32];

    const int tid  = threadIdx.x;
    const int lane = tid & 31;
    const int warp = tid >> 5;               // 0..7
    const int row  = blockIdx.x;

    const uint32_t mbar_a = (uint32_t)__cvta_generic_to_shared(&mbar);
    const uint32_t sbuf_a = (uint32_t)__cvta_generic_to_shared(&sbuf[0]);

    // ── Phase 0: init mbarrier, then fire the TMA bulk copy ──────────────
    if (tid == 0) {
        asm volatile("mbarrier.init.shared.b64 [%0], 1;" :: "r"(mbar_a) : "memory");
    }
    __syncthreads();
    if (tid == 0) {
        const int* grow = gesture + (size_t)row * T_LEN;
        asm volatile("mbarrier.arrive.expect_tx.shared.b64 _, [%0], %1;"
                     :: "r"(mbar_a), "r"((uint32_t)ROW_BYTES) : "memory");
        asm volatile(
            "cp.async.bulk.shared::cluster.global.mbarrier::complete_tx::bytes "
            "[%0], [%1], %2, [%3];"
            :: "r"(sbuf_a), "l"(grow), "r"((uint32_t)ROW_BYTES), "r"(mbar_a)
            : "memory");
    }

    // ── Wait for the row to land in shared (HW-sleep try_wait loop) ──────
    {
        uint32_t done;
        asm volatile(
            "{\n\t"
            ".reg .pred p;\n\t"
            "mbarrier.try_wait.parity.acquire.cta.shared::cta.b64 p, [%1], 0;\n\t"
            "selp.b32 %0, 1, 0, p;\n\t"
            "}" : "=r"(done) : "r"(mbar_a) : "memory");
        if (!done) {
            asm volatile(
                "{\n\t"
                ".reg .pred P1;\n\t"
                "WAIT_LOOP_%=:\n\t"
                "mbarrier.try_wait.parity.acquire.cta.shared::cta.b64 P1, [%0], 0, 0x989680;\n\t"
                "@P1 bra.uni WAIT_DONE_%=;\n\t"
                "bra.uni WAIT_LOOP_%=;\n\t"
                "WAIT_DONE_%=:\n\t"
                "}" :: "r"(mbar_a) : "memory");
        }
    }

    // ── Phase 1: read row from shared + ballot packing (same as best) ────
    // Warp w covers chunks {w, 8+w, 16+w, 24+w}; lane l reads int4 of
    // elements [c*128 + 4l, c*128 + 4l + 4). LDS.128, conflict-free.
    int4 g[4];
#pragma unroll
    for (int i = 0; i < 4; i++)
        g[i] = sbuf[(i * 8 + warp) * 32 + lane];

#pragma unroll
    for (int i = 0; i < 4; i++) {
        const int c = i * 8 + warp;
        const uint32_t b0 = __ballot_sync(0xffffffffu, g[i].x == 2);
        const uint32_t b1 = __ballot_sync(0xffffffffu, g[i].y == 2);
        const uint32_t b2 = __ballot_sync(0xffffffffu, g[i].z == 2);
        const uint32_t b3 = __ballot_sync(0xffffffffu, g[i].w == 2);
        if (lane == 0) {
            sball[c * 4 + 0] = b0;
            sball[c * 4 + 1] = b1;
            sball[c * 4 + 2] = b2;
            sball[c * 4 + 3] = b3;
        }
    }
    __syncthreads();

    // ── Phase 2: per-word streak counting (threads 0..127) ───────────────
    // Each thread de-interleaves its own mask word AND the next word from
    // the raw ballots. A streak of length >= L exists iff some start
    // (m[t] && !m[t-1]) has m[t..t+L-1] all set; window <= 6 ahead, 1 behind.
    int packed = 0;   // hc | (lc << 16)
    if (tid < WORDS) {
        const int w = tid;
        uint32_t wcur = 0, wnxt = 0;
        {
            const int c = w >> 2, j = w & 3;
#pragma unroll
            for (int k = 0; k < 4; k++)
                wcur |= spread4(sball[c * 4 + k] >> (8 * j)) << k;
        }
        if (w + 1 < WORDS) {
            const int c = (w + 1) >> 2, j = (w + 1) & 3;
#pragma unroll
            for (int k = 0; k < 4; k++)
                wnxt |= spread4(sball[c * 4 + k] >> (8 * j)) << k;
        }
        uint32_t prevbit = 0;
        if (w > 0) {
            const int c = (w - 1) >> 2, j = (w - 1) & 3;
            // bit 31 of word w-1 = ballot 3, bit 8j+7
            prevbit = (sball[c * 4 + 3] >> (8 * j + 7)) & 1u;
        }

        const uint64_t ext = ((uint64_t)wnxt << 32) | (uint64_t)wcur;
        const uint32_t starts = wcur & ~((wcur << 1) | prevbit);
        const uint64_t r4 = ext & (ext >> 1) & (ext >> 2) & (ext >> 3);
        const uint64_t r7 = r4  & (ext >> 4) & (ext >> 5) & (ext >> 6);

        packed = __popc(starts & (uint32_t)r4)
               | (__popc(starts & (uint32_t)r7) << 16);
    }

    // ── Phase 3: block reduction + epilogue ──────────────────────────────
#pragma unroll
    for (int off = 16; off > 0; off >>= 1)
        packed += __shfl_down_sync(0xffffffffu, packed, off);
    if (lane == 0) sred[warp] = packed;
    __syncthreads();

    if (tid == 0) {
        int tot = 0;
#pragma unroll
        for (int i = 0; i < THREADS / 32; i++) tot += sred[i];
        const int hc = tot & 0xffff;
        const int lc = tot >> 16;

        float hadj = (hc >= 2) ? 0.18f * expf(-0.5f * (float)(hc - 2)) : 0.0f;
        float ladj = (lc >= 3) ? 0.05f * expf(-0.5f * (float)(lc - 3)) : 0.0f;
        float adj = fminf(hadj + ladj, 0.35f);
        float r = drowsiness[row] + adj;
        out[row] = fminf(fmaxf(r, 0.0f), 1.0f);
    }
}

extern "C" void kernel_launch(void* const* d_in, const int* in_sizes, int n_in,
                              void* d_out, int out_size)
{
    const float* drowsiness = (const float*)d_in[0];   // [B, 1] fp32
    const int*   gesture    = (const int*)d_in[1];     // [B, T, 1] int32
    float*       out        = (float*)d_out;           // [B, 1] fp32
    (void)in_sizes; (void)n_in; (void)out_size;

    yawning_adjust_kernel<<<B_ROWS, THREADS>>>(drowsiness, gesture, out);
}

// round 13
// speedup vs baseline: 1.0522x; 1.0522x over previous
#include <cuda_runtime.h>
#include <cstdint>

// Problem constants (fixed shapes from reference)
#define B_ROWS 16384
#define T_LEN  4096
#define WORDS  (T_LEN / 32)    // 128 mask words per row
#define CH256  (T_LEN / 256)   // 16 chunks of 256 elems per row
#define THREADS 256

// Spread 4 bits (positions 0..3) to positions 0,8,16,24.
__device__ __forceinline__ uint32_t spread8(uint32_t x)
{
    x &= 0xFu;
    x = (x | (x << 14)) & 0x00030003u;
    x = (x | (x << 7))  & 0x01010101u;
    return x;
}

// 256-bit global load (LDG.E.256, sm_100a+). p must be 32B-aligned.
__device__ __forceinline__ void ldg256(const int* __restrict__ p, uint32_t r[8])
{
    asm volatile("ld.global.nc.v8.b32 {%0,%1,%2,%3,%4,%5,%6,%7}, [%8];"
                 : "=r"(r[0]), "=r"(r[1]), "=r"(r[2]), "=r"(r[3]),
                   "=r"(r[4]), "=r"(r[5]), "=r"(r[6]), "=r"(r[7])
                 : "l"(p));
}

__global__ void __launch_bounds__(THREADS)
yawning_adjust_kernel(const float* __restrict__ drowsiness,
                      const int* __restrict__ gesture,
                      float* __restrict__ out)
{
    __shared__ uint32_t sball[CH256 * 8];   // raw interleaved ballots
    __shared__ int      sred[THREADS / 32];

    const int tid  = threadIdx.x;
    const int lane = tid & 31;
    const int warp = tid >> 5;               // 0..7
    const int row  = blockIdx.x;

    const int* __restrict__ grow = gesture + (size_t)row * T_LEN;

    // ── Phase 1: two LDG.256 per thread (64 B), both issued before use ───
    // Warp w covers 256-elem chunks {w, 8+w}; lane l loads elems
    // [c*256 + 8l, c*256 + 8l + 8). Fully coalesced 1 KB per warp-instr.
    uint32_t a[8], b[8];
    ldg256(grow + (warp)     * 256 + lane * 8, a);
    ldg256(grow + (8 + warp) * 256 + lane * 8, b);

    // ── Phase 2: ballot packing. Ballot k of chunk c holds, at bit `lane`,
    // the yawning flag of elem c*256 + 8*lane + k.
#pragma unroll
    for (int k = 0; k < 8; k++) {
        const uint32_t bk = __ballot_sync(0xffffffffu, a[k] == 2);
        if (lane == 0) sball[warp * 8 + k] = bk;
    }
#pragma unroll
    for (int k = 0; k < 8; k++) {
        const uint32_t bk = __ballot_sync(0xffffffffu, b[k] == 2);
        if (lane == 0) sball[(8 + warp) * 8 + k] = bk;
    }
    __syncthreads();

    // ── Phase 3: per-word streak counting (threads 0..127) ───────────────
    // Word w covers elems [32w, 32w+32): chunk c = w>>3, j = w&7, built from
    // lanes 4j..4j+3 of the 8 ballots; ballot k's lane (4j+i) bit -> word
    // bit 8i+k. Each thread de-interleaves its own word AND the next word.
    // A streak of length >= L exists iff some start (m[t] && !m[t-1]) has
    // m[t..t+L-1] all set; window <= 6 bits ahead, 1 bit behind.
    int packed = 0;   // hc | (lc << 16)
    if (tid < WORDS) {
        const int w = tid;
        uint32_t wcur = 0, wnxt = 0;
        {
            const int c = w >> 3, j = w & 7;
#pragma unroll
            for (int k = 0; k < 8; k++)
                wcur |= spread8(sball[c * 8 + k] >> (4 * j)) << k;
        }
        if (w + 1 < WORDS) {
            const int c = (w + 1) >> 3, j = (w + 1) & 7;
#pragma unroll
            for (int k = 0; k < 8; k++)
                wnxt |= spread8(sball[c * 8 + k] >> (4 * j)) << k;
        }
        uint32_t prevbit = 0;
        if (w > 0) {
            const int c = (w - 1) >> 3, j = (w - 1) & 7;
            // bit 31 of word w-1: i=3, k=7 -> ballot 7, lane 4j+3
            prevbit = (sball[c * 8 + 7] >> (4 * j + 3)) & 1u;
        }

        const uint64_t ext = ((uint64_t)wnxt << 32) | (uint64_t)wcur;
        const uint32_t starts = wcur & ~((wcur << 1) | prevbit);
        const uint64_t r4 = ext & (ext >> 1) & (ext >> 2) & (ext >> 3);
        const uint64_t r7 = r4  & (ext >> 4) & (ext >> 5) & (ext >> 6);

        packed = __popc(starts & (uint32_t)r4)
               | (__popc(starts & (uint32_t)r7) << 16);
    }

    // ── Phase 4: block reduction + epilogue ──────────────────────────────
#pragma unroll
    for (int off = 16; off > 0; off >>= 1)
        packed += __shfl_down_sync(0xffffffffu, packed, off);
    if (lane == 0) sred[warp] = packed;
    __syncthreads();

    if (tid == 0) {
        int tot = 0;
#pragma unroll
        for (int i = 0; i < THREADS / 32; i++) tot += sred[i];
        const int hc = tot & 0xffff;
        const int lc = tot >> 16;

        float hadj = (hc >= 2) ? 0.18f * expf(-0.5f * (float)(hc - 2)) : 0.0f;
        float ladj = (lc >= 3) ? 0.05f * expf(-0.5f * (float)(lc - 3)) : 0.0f;
        float adj = fminf(hadj + ladj, 0.35f);
        float r = drowsiness[row] + adj;
        out[row] = fminf(fmaxf(r, 0.0f), 1.0f);
    }
}

extern "C" void kernel_launch(void* const* d_in, const int* in_sizes, int n_in,
                              void* d_out, int out_size)
{
    const float* drowsiness = (const float*)d_in[0];   // [B, 1] fp32
    const int*   gesture    = (const int*)d_in[1];     // [B, T, 1] int32
    float*       out        = (float*)d_out;           // [B, 1] fp32
    (void)in_sizes; (void)n_in; (void)out_size;

    yawning_adjust_kernel<<<B_ROWS, THREADS>>>(drowsiness, gesture, out);
}